// round 9
// baseline (speedup 1.0000x reference)
#include <cuda_runtime.h>

// SSIM loss, fused single pass. img1,img2: [32,1,1024,1024] f32; 11x11 uniform
// window (1/121) constant-folded. out: scalar f32 = 1 - mean(ssim_map).
//
// Design (R5, frozen pending first successful bench):
//  - grid = 32 images x 16 row-strips (HS=64). Block = 128 threads, each owns
//    TX=8 consecutive columns (block spans full width 1024).
//  - Vertical box sums: per-thread PACKED (f32x2) register running sums over 5
//    quantities (x1, x2, x1^2, x2^2, x1*x2), slid by +row(y+5) - row(y-5).
//    Trailing subtraction via sign-flip (u64 XOR) + add/fma (one rounding).
//  - Trailing-row LDGs issued BEFORE the barrier + horizontal phase so their
//    L1/L2 latency overlaps ~80 instructions of LDS/FMA work.
//  - Horizontal box sums: column sums published to shared sh[y&1][q][x+PAD],
//    aligned float4 LDS/STS (conflict-free). 11-tap for the first output
//    column, O(1) slide for the remaining 7. Zero padding via zeroed borders.
//  - Double buffer -> one __syncthreads per row.
//  - Deterministic reduction: warp shfl -> g_partials[512] -> finalize kernel.

#define W 1024
#define H 1024
#define NIMG 32
#define HS 64
#define NSTRIP (H / HS)          // 16
#define NBLK (NIMG * NSTRIP)     // 512
#define TPB 128
#define TX 8
#define PADX 8
#define SHW (W + 2 * PADX)       // 1040

typedef unsigned long long u64;

#define F2SIGN 0x8000000080000000ULL

// Packed f32x2 ops (sm_100+ PTX). Both mnemonics are verified in-tree:
// add.rn.f32x2 in ptx_helpers.cuh ADD_F32X2; fma.rn.f32x2 per SASS_QUICKREF
// ("FFMA2 from C++ only via PTX fma.rn.f32x2").
#define F2ADD(d, a, b)    asm("add.rn.f32x2 %0, %1, %2;"     : "=l"(d) : "l"(a), "l"(b))
#define F2FMA(d, a, b, c) asm("fma.rn.f32x2 %0, %1, %2, %3;" : "=l"(d) : "l"(a), "l"(b), "l"(c))

__device__ float g_partials[NBLK];

__global__ __launch_bounds__(TPB)
void ssim_main_kernel(const float* __restrict__ img1, const float* __restrict__ img2) {
    __shared__ float sh[2][5][SHW];       // 41600 B
    __shared__ float red[TPB / 32];

    const int tid   = threadIdx.x;
    const int bid   = blockIdx.x;
    const int img   = bid / NSTRIP;
    const int strip = bid % NSTRIP;
    const int y0    = strip * HS;

    const float* p1 = img1 + (size_t)img * (H * W);
    const float* p2 = img2 + (size_t)img * (H * W);
    const int c0 = tid * TX;

    // Zero both buffers once: border cells (never re-written) must read as 0.
    {
        float4* shv = (float4*)&sh[0][0][0];
        for (int i = tid; i < (2 * 5 * SHW) / 4; i += TPB)
            shv[i] = make_float4(0.f, 0.f, 0.f, 0.f);
    }

    // Packed per-thread vertical running sums: 5 quantities x 4 column-pairs.
    u64 cs1[4], cs2[4], cs11[4], cs22[4], cs12[4];
#pragma unroll
    for (int k = 0; k < 4; k++)
        cs1[k] = cs2[k] = cs11[k] = cs22[k] = cs12[k] = 0ULL;

    // Warm-up rows y0-5 .. y0+4 (zero padded outside image).
    for (int r = y0 - 5; r <= y0 + 4; ++r) {
        if ((unsigned)r < H) {
            const ulonglong2* a2 = (const ulonglong2*)(p1 + (size_t)r * W + c0);
            const ulonglong2* b2 = (const ulonglong2*)(p2 + (size_t)r * W + c0);
            ulonglong2 al = a2[0], ah = a2[1], bl = b2[0], bh = b2[1];
            u64 ap[4] = {al.x, al.y, ah.x, ah.y};
            u64 bp[4] = {bl.x, bl.y, bh.x, bh.y};
#pragma unroll
            for (int k = 0; k < 4; k++) {
                F2ADD(cs1[k],  cs1[k],  ap[k]);
                F2ADD(cs2[k],  cs2[k],  bp[k]);
                F2FMA(cs11[k], ap[k], ap[k], cs11[k]);
                F2FMA(cs22[k], bp[k], bp[k], cs22[k]);
                F2FMA(cs12[k], ap[k], bp[k], cs12[k]);
            }
        }
    }
    __syncthreads();   // zero-init of sh visible to all

    float acc = 0.0f;
    const float kinv = 1.0f / 121.0f;
    const float C1 = 0.0001f;   // 0.01^2
    const float C2 = 0.0009f;   // 0.03^2

    for (int y = y0; y < y0 + HS; ++y) {
        const int buf = y & 1;

        // --- add fresh row y+5 (packed) ---
        const int rf = y + 5;
        if (rf < H) {
            const ulonglong2* a2 = (const ulonglong2*)(p1 + (size_t)rf * W + c0);
            const ulonglong2* b2 = (const ulonglong2*)(p2 + (size_t)rf * W + c0);
            ulonglong2 al = a2[0], ah = a2[1], bl = b2[0], bh = b2[1];
            u64 ap[4] = {al.x, al.y, ah.x, ah.y};
            u64 bp[4] = {bl.x, bl.y, bh.x, bh.y};
#pragma unroll
            for (int k = 0; k < 4; k++) {
                F2ADD(cs1[k],  cs1[k],  ap[k]);
                F2ADD(cs2[k],  cs2[k],  bp[k]);
                F2FMA(cs11[k], ap[k], ap[k], cs11[k]);
                F2FMA(cs22[k], bp[k], bp[k], cs22[k]);
                F2FMA(cs12[k], ap[k], bp[k], cs12[k]);
            }
        }

        // --- HOISTED trailing-row (y-5) loads: issue LDGs now so the L1/L2
        //     latency overlaps the barrier + horizontal + SSIM phases. ---
        const int ro = y - 5;
        u64 tap[4], tbp[4];
        if (ro >= 0) {
            const ulonglong2* a2 = (const ulonglong2*)(p1 + (size_t)ro * W + c0);
            const ulonglong2* b2 = (const ulonglong2*)(p2 + (size_t)ro * W + c0);
            ulonglong2 al = a2[0], ah = a2[1], bl = b2[0], bh = b2[1];
            tap[0] = al.x; tap[1] = al.y; tap[2] = ah.x; tap[3] = ah.y;
            tbp[0] = bl.x; tbp[1] = bl.y; tbp[2] = bh.x; tbp[3] = bh.y;
        }

        // --- publish column sums (2 x STS.128 per quantity) ---
        {
            ulonglong2* d;
            d = (ulonglong2*)&sh[buf][0][PADX + c0];
            d[0] = make_ulonglong2(cs1[0], cs1[1]);
            d[1] = make_ulonglong2(cs1[2], cs1[3]);
            d = (ulonglong2*)&sh[buf][1][PADX + c0];
            d[0] = make_ulonglong2(cs2[0], cs2[1]);
            d[1] = make_ulonglong2(cs2[2], cs2[3]);
            d = (ulonglong2*)&sh[buf][2][PADX + c0];
            d[0] = make_ulonglong2(cs11[0], cs11[1]);
            d[1] = make_ulonglong2(cs11[2], cs11[3]);
            d = (ulonglong2*)&sh[buf][3][PADX + c0];
            d[0] = make_ulonglong2(cs22[0], cs22[1]);
            d[1] = make_ulonglong2(cs22[2], cs22[3]);
            d = (ulonglong2*)&sh[buf][4][PADX + c0];
            d[0] = make_ulonglong2(cs12[0], cs12[1]);
            d[1] = make_ulonglong2(cs12[2], cs12[3]);
        }
        __syncthreads();   // only barrier per row (double buffer covers WAR)

        // --- horizontal 11-sum with sliding window (6 x LDS.128 per q) ---
        // v[0..23] = sh[buf][q][PADX + c0 - 8 .. PADX + c0 + 15]
        // output j (col c0+j): sum = v[j+3 .. j+13]
        float S[5][TX];
#pragma unroll
        for (int q = 0; q < 5; q++) {
            const float4* s4 = (const float4*)&sh[buf][q][PADX + c0 - 8];  // aligned
            float v[24];
#pragma unroll
            for (int t = 0; t < 6; t++) {
                float4 x = s4[t];
                v[4*t+0] = x.x; v[4*t+1] = x.y; v[4*t+2] = x.z; v[4*t+3] = x.w;
            }
            float s = 0.0f;
#pragma unroll
            for (int k = 3; k <= 13; ++k) s += v[k];
            S[q][0] = s;
#pragma unroll
            for (int j = 1; j < TX; j++) {
                s += v[j + 13] - v[j + 2];
                S[q][j] = s;
            }
        }

        // --- SSIM per output pixel ---
#pragma unroll
        for (int j = 0; j < TX; j++) {
            float mu1  = S[0][j] * kinv;
            float mu2  = S[1][j] * kinv;
            float mu1s = mu1 * mu1;
            float mu2s = mu2 * mu2;
            float mu12 = mu1 * mu2;
            float s1   = fmaf(S[2][j], kinv, -mu1s);
            float s2   = fmaf(S[3][j], kinv, -mu2s);
            float s12  = fmaf(S[4][j], kinv, -mu12);
            float num  = fmaf(2.0f, mu12, C1) * fmaf(2.0f, s12, C2);
            float den  = (mu1s + mu2s + C1) * (s1 + s2 + C2);
            acc += __fdividef(num, den);
        }

        // --- apply trailing-row subtraction (values already in registers) ---
        if (ro >= 0) {
#pragma unroll
            for (int k = 0; k < 4; k++) {
                const u64 nap = tap[k] ^ F2SIGN;   // (-a, -a) packed (ALU pipe)
                const u64 nbp = tbp[k] ^ F2SIGN;   // (-b, -b) packed
                F2ADD(cs1[k],  cs1[k],  nap);
                F2ADD(cs2[k],  cs2[k],  nbp);
                F2FMA(cs11[k], nap, tap[k], cs11[k]);   // cs11 - a*a
                F2FMA(cs22[k], nbp, tbp[k], cs22[k]);   // cs22 - b*b
                F2FMA(cs12[k], nap, tbp[k], cs12[k]);   // cs12 - a*b
            }
        }
        // no second barrier: next row writes the other buffer
    }

    // --- deterministic block reduction (4 warps) ---
#pragma unroll
    for (int o = 16; o; o >>= 1)
        acc += __shfl_down_sync(0xFFFFFFFFu, acc, o);
    if ((tid & 31) == 0)
        red[tid >> 5] = acc;
    __syncthreads();
    if (tid == 0) {
        float s = 0.0f;
#pragma unroll
        for (int i = 0; i < TPB / 32; i++)
            s += red[i];
        g_partials[bid] = s;
    }
}

__global__ void ssim_finalize_kernel(float* __restrict__ out) {
    const int t = threadIdx.x;   // 512 threads = NBLK partials
    float v = g_partials[t];
#pragma unroll
    for (int o = 16; o; o >>= 1)
        v += __shfl_down_sync(0xFFFFFFFFu, v, o);
    __shared__ float shred[16];
    if ((t & 31) == 0)
        shred[t >> 5] = v;
    __syncthreads();
    if (t < 16) {
        float w = shred[t];
#pragma unroll
        for (int o = 8; o; o >>= 1)
            w += __shfl_down_sync(0x0000FFFFu, w, o);
        if (t == 0)
            out[0] = 1.0f - w / 33554432.0f;   // 32*1024*1024
    }
}

extern "C" void kernel_launch(void* const* d_in, const int* in_sizes, int n_in,
                              void* d_out, int out_size) {
    const float* img1 = (const float*)d_in[0];
    const float* img2 = (const float*)d_in[1];
    // d_in[2]: uniform 1/121 window, constant-folded.
    (void)in_sizes; (void)n_in; (void)out_size;

    ssim_main_kernel<<<NBLK, TPB>>>(img1, img2);
    ssim_finalize_kernel<<<1, NBLK>>>((float*)d_out);
}

// round 11
// speedup vs baseline: 1.0082x; 1.0082x over previous
#include <cuda_runtime.h>

// SSIM loss, fused single pass. img1,img2: [32,1,1024,1024] f32; 11x11 uniform
// window (1/121) constant-folded. out: scalar f32 = 1 - mean(ssim_map).
//
// Design (R6 = R5 + fresh-row software pipeline + HS=32 load balance):
//  - grid = 32 images x 32 row-strips (HS=32) = 1024 blocks (tail imbalance
//    ~2% vs 25% at 512 blocks). Block = 128 threads, each owns TX=8 columns.
//  - Vertical box sums: packed f32x2 register running sums over 5 quantities,
//    slid by +row(y+5) - row(y-5). FRESH row is SOFTWARE-PIPELINED: row y+5
//    is loaded during iteration y-1, so its DRAM latency (~400-600 cyc) is
//    hidden behind a full row of work. Trailing row (L2 hit) loaded early in
//    the iteration, consumed after the SSIM phase.
//  - Horizontal box sums: column sums via shared sh[y&1][q][x+PAD], aligned
//    float4 LDS/STS (conflict-free); 11-tap then O(1) slide. Double buffer ->
//    one __syncthreads per row.
//  - Deterministic reduction: warp shfl -> g_partials[1024] -> finalize.

#define W 1024
#define H 1024
#define NIMG 32
#define HS 32
#define NSTRIP (H / HS)          // 32
#define NBLK (NIMG * NSTRIP)     // 1024
#define TPB 128
#define TX 8
#define PADX 8
#define SHW (W + 2 * PADX)       // 1040

typedef unsigned long long u64;

#define F2SIGN 0x8000000080000000ULL

// Packed f32x2 ops (sm_100+ PTX; mnemonics verified in-tree).
#define F2ADD(d, a, b)    asm("add.rn.f32x2 %0, %1, %2;"     : "=l"(d) : "l"(a), "l"(b))
#define F2FMA(d, a, b, c) asm("fma.rn.f32x2 %0, %1, %2, %3;" : "=l"(d) : "l"(a), "l"(b), "l"(c))

__device__ float g_partials[NBLK];

__global__ __launch_bounds__(TPB, 4)
void ssim_main_kernel(const float* __restrict__ img1, const float* __restrict__ img2) {
    __shared__ float sh[2][5][SHW];       // 41600 B
    __shared__ float red[TPB / 32];

    const int tid   = threadIdx.x;
    const int bid   = blockIdx.x;
    const int img   = bid / NSTRIP;
    const int strip = bid % NSTRIP;
    const int y0    = strip * HS;

    const float* p1 = img1 + (size_t)img * (H * W);
    const float* p2 = img2 + (size_t)img * (H * W);
    const int c0 = tid * TX;

    // Zero both buffers once: border cells (never re-written) must read as 0.
    {
        float4* shv = (float4*)&sh[0][0][0];
        for (int i = tid; i < (2 * 5 * SHW) / 4; i += TPB)
            shv[i] = make_float4(0.f, 0.f, 0.f, 0.f);
    }

    // Packed per-thread vertical running sums: 5 quantities x 4 column-pairs.
    u64 cs1[4], cs2[4], cs11[4], cs22[4], cs12[4];
#pragma unroll
    for (int k = 0; k < 4; k++)
        cs1[k] = cs2[k] = cs11[k] = cs22[k] = cs12[k] = 0ULL;

    // Warm-up rows y0-5 .. y0+4 (zero padded outside image).
    for (int r = y0 - 5; r <= y0 + 4; ++r) {
        if ((unsigned)r < H) {
            const ulonglong2* a2 = (const ulonglong2*)(p1 + (size_t)r * W + c0);
            const ulonglong2* b2 = (const ulonglong2*)(p2 + (size_t)r * W + c0);
            ulonglong2 al = a2[0], ah = a2[1], bl = b2[0], bh = b2[1];
            u64 ap[4] = {al.x, al.y, ah.x, ah.y};
            u64 bp[4] = {bl.x, bl.y, bh.x, bh.y};
#pragma unroll
            for (int k = 0; k < 4; k++) {
                F2ADD(cs1[k],  cs1[k],  ap[k]);
                F2ADD(cs2[k],  cs2[k],  bp[k]);
                F2FMA(cs11[k], ap[k], ap[k], cs11[k]);
                F2FMA(cs22[k], bp[k], bp[k], cs22[k]);
                F2FMA(cs12[k], ap[k], bp[k], cs12[k]);
            }
        }
    }

    // Software-pipeline primer: pa/pb hold row y+5 for the FIRST iteration
    // (zeros if out of range -> adding packed +0 is harmless).
    u64 pa[4] = {0, 0, 0, 0}, pb[4] = {0, 0, 0, 0};
    if (y0 + 5 < H) {
        const ulonglong2* a2 = (const ulonglong2*)(p1 + (size_t)(y0 + 5) * W + c0);
        const ulonglong2* b2 = (const ulonglong2*)(p2 + (size_t)(y0 + 5) * W + c0);
        ulonglong2 al = a2[0], ah = a2[1], bl = b2[0], bh = b2[1];
        pa[0] = al.x; pa[1] = al.y; pa[2] = ah.x; pa[3] = ah.y;
        pb[0] = bl.x; pb[1] = bl.y; pb[2] = bh.x; pb[3] = bh.y;
    }
    __syncthreads();   // zero-init of sh visible to all

    float acc = 0.0f;
    const float kinv = 1.0f / 121.0f;
    const float C1 = 0.0001f;   // 0.01^2
    const float C2 = 0.0009f;   // 0.03^2

    for (int y = y0; y < y0 + HS; ++y) {
        const int buf = y & 1;

        // --- consume pipelined fresh row y+5 (already in registers) ---
#pragma unroll
        for (int k = 0; k < 4; k++) {
            F2ADD(cs1[k],  cs1[k],  pa[k]);
            F2ADD(cs2[k],  cs2[k],  pb[k]);
            F2FMA(cs11[k], pa[k], pa[k], cs11[k]);
            F2FMA(cs22[k], pb[k], pb[k], cs22[k]);
            F2FMA(cs12[k], pa[k], pb[k], cs12[k]);
        }

        // --- PREFETCH next fresh row y+6 (DRAM latency spans the whole
        //     remaining iteration: publish + barrier + horizontal + SSIM) ---
        u64 npa[4] = {0, 0, 0, 0}, npb[4] = {0, 0, 0, 0};
        if (y + 6 < H) {
            const ulonglong2* a2 = (const ulonglong2*)(p1 + (size_t)(y + 6) * W + c0);
            const ulonglong2* b2 = (const ulonglong2*)(p2 + (size_t)(y + 6) * W + c0);
            ulonglong2 al = a2[0], ah = a2[1], bl = b2[0], bh = b2[1];
            npa[0] = al.x; npa[1] = al.y; npa[2] = ah.x; npa[3] = ah.y;
            npb[0] = bl.x; npb[1] = bl.y; npb[2] = bh.x; npb[3] = bh.y;
        }

        // --- hoisted trailing-row (y-5) loads (L2 hit, consumed post-SSIM) ---
        const int ro = y - 5;
        u64 tap[4], tbp[4];
        if (ro >= 0) {
            const ulonglong2* a2 = (const ulonglong2*)(p1 + (size_t)ro * W + c0);
            const ulonglong2* b2 = (const ulonglong2*)(p2 + (size_t)ro * W + c0);
            ulonglong2 al = a2[0], ah = a2[1], bl = b2[0], bh = b2[1];
            tap[0] = al.x; tap[1] = al.y; tap[2] = ah.x; tap[3] = ah.y;
            tbp[0] = bl.x; tbp[1] = bl.y; tbp[2] = bh.x; tbp[3] = bh.y;
        }

        // --- publish column sums (2 x STS.128 per quantity) ---
        {
            ulonglong2* d;
            d = (ulonglong2*)&sh[buf][0][PADX + c0];
            d[0] = make_ulonglong2(cs1[0], cs1[1]);
            d[1] = make_ulonglong2(cs1[2], cs1[3]);
            d = (ulonglong2*)&sh[buf][1][PADX + c0];
            d[0] = make_ulonglong2(cs2[0], cs2[1]);
            d[1] = make_ulonglong2(cs2[2], cs2[3]);
            d = (ulonglong2*)&sh[buf][2][PADX + c0];
            d[0] = make_ulonglong2(cs11[0], cs11[1]);
            d[1] = make_ulonglong2(cs11[2], cs11[3]);
            d = (ulonglong2*)&sh[buf][3][PADX + c0];
            d[0] = make_ulonglong2(cs22[0], cs22[1]);
            d[1] = make_ulonglong2(cs22[2], cs22[3]);
            d = (ulonglong2*)&sh[buf][4][PADX + c0];
            d[0] = make_ulonglong2(cs12[0], cs12[1]);
            d[1] = make_ulonglong2(cs12[2], cs12[3]);
        }
        __syncthreads();   // only barrier per row (double buffer covers WAR)

        // --- horizontal 11-sum with sliding window (6 x LDS.128 per q) ---
        float S[5][TX];
#pragma unroll
        for (int q = 0; q < 5; q++) {
            const float4* s4 = (const float4*)&sh[buf][q][PADX + c0 - 8];  // aligned
            float v[24];
#pragma unroll
            for (int t = 0; t < 6; t++) {
                float4 x = s4[t];
                v[4*t+0] = x.x; v[4*t+1] = x.y; v[4*t+2] = x.z; v[4*t+3] = x.w;
            }
            float s = 0.0f;
#pragma unroll
            for (int k = 3; k <= 13; ++k) s += v[k];
            S[q][0] = s;
#pragma unroll
            for (int j = 1; j < TX; j++) {
                s += v[j + 13] - v[j + 2];
                S[q][j] = s;
            }
        }

        // --- SSIM per output pixel ---
#pragma unroll
        for (int j = 0; j < TX; j++) {
            float mu1  = S[0][j] * kinv;
            float mu2  = S[1][j] * kinv;
            float mu1s = mu1 * mu1;
            float mu2s = mu2 * mu2;
            float mu12 = mu1 * mu2;
            float s1   = fmaf(S[2][j], kinv, -mu1s);
            float s2   = fmaf(S[3][j], kinv, -mu2s);
            float s12  = fmaf(S[4][j], kinv, -mu12);
            float num  = fmaf(2.0f, mu12, C1) * fmaf(2.0f, s12, C2);
            float den  = (mu1s + mu2s + C1) * (s1 + s2 + C2);
            acc += __fdividef(num, den);
        }

        // --- apply trailing-row subtraction (values already in registers) ---
        if (ro >= 0) {
#pragma unroll
            for (int k = 0; k < 4; k++) {
                const u64 nap = tap[k] ^ F2SIGN;   // (-a, -a) packed (ALU pipe)
                const u64 nbp = tbp[k] ^ F2SIGN;   // (-b, -b) packed
                F2ADD(cs1[k],  cs1[k],  nap);
                F2ADD(cs2[k],  cs2[k],  nbp);
                F2FMA(cs11[k], nap, tap[k], cs11[k]);   // cs11 - a*a
                F2FMA(cs22[k], nbp, tbp[k], cs22[k]);   // cs22 - b*b
                F2FMA(cs12[k], nap, tbp[k], cs12[k]);   // cs12 - a*b
            }
        }

        // --- rotate fresh-row pipeline ---
#pragma unroll
        for (int k = 0; k < 4; k++) { pa[k] = npa[k]; pb[k] = npb[k]; }
        // no second barrier: next row writes the other buffer
    }

    // --- deterministic block reduction (4 warps) ---
#pragma unroll
    for (int o = 16; o; o >>= 1)
        acc += __shfl_down_sync(0xFFFFFFFFu, acc, o);
    if ((tid & 31) == 0)
        red[tid >> 5] = acc;
    __syncthreads();
    if (tid == 0) {
        float s = 0.0f;
#pragma unroll
        for (int i = 0; i < TPB / 32; i++)
            s += red[i];
        g_partials[bid] = s;
    }
}

__global__ void ssim_finalize_kernel(float* __restrict__ out) {
    const int t = threadIdx.x;   // 1024 threads = NBLK partials
    float v = g_partials[t];
#pragma unroll
    for (int o = 16; o; o >>= 1)
        v += __shfl_down_sync(0xFFFFFFFFu, v, o);
    __shared__ float shred[32];
    if ((t & 31) == 0)
        shred[t >> 5] = v;
    __syncthreads();
    if (t < 32) {
        float w = shred[t];
#pragma unroll
        for (int o = 16; o; o >>= 1)
            w += __shfl_down_sync(0xFFFFFFFFu, w, o);
        if (t == 0)
            out[0] = 1.0f - w / 33554432.0f;   // 32*1024*1024
    }
}

extern "C" void kernel_launch(void* const* d_in, const int* in_sizes, int n_in,
                              void* d_out, int out_size) {
    const float* img1 = (const float*)d_in[0];
    const float* img2 = (const float*)d_in[1];
    // d_in[2]: uniform 1/121 window, constant-folded.
    (void)in_sizes; (void)n_in; (void)out_size;

    ssim_main_kernel<<<NBLK, TPB>>>(img1, img2);
    ssim_finalize_kernel<<<1, NBLK>>>((float*)d_out);
}